// round 7
// baseline (speedup 1.0000x reference)
#include <cuda_runtime.h>
#include <cstdint>

#define D_IN   128
#define D_OUT  64
#define D_EDGE 11
#define NMAX   100000
#define EMAX   1000000
#define NEG_SLOPE 0.2f
#define SCAN_BLK 512

// Scratch: ONLY referenced from device code (host-side use of a __device__
// symbol passes the host shadow address; ATS silently dereferences it).
__device__ float  g_xl[(size_t)NMAX * D_OUT];     // x @ W_l
__device__ float  g_xr[(size_t)NMAX * D_OUT];     // x @ W_r
__device__ float4 g_ea16[(size_t)EMAX * 3];       // edge_attr padded to 48B rows
__device__ int2   g_sd[EMAX];                     // decoded (src, dst)
__device__ int2   g_csr[EMAX];                    // CSR payload: (src, eid)
__device__ int    g_cnt[NMAX];                    // in-degree counts
__device__ int    g_off[NMAX];                    // CSR offsets
__device__ int    g_cursor[NMAX];                 // scatter cursors
__device__ int    g_bsum[(NMAX + SCAN_BLK - 1) / SCAN_BLK];
__device__ int    g_is64;
__device__ int    g_diag;

// ---------------------------------------------------------------------------
__global__ void init_kernel(int n) {
    int stride = gridDim.x * blockDim.x;
    int tid0 = blockIdx.x * blockDim.x + threadIdx.x;
    if (tid0 == 0) g_diag = 0;
    for (int i = tid0; i < n; i += stride) g_cnt[i] = 0;
}

__global__ void set_diag_kernel(int bits) {
    if (threadIdx.x == 0) atomicOr(&g_diag, bits);
}

// Detect int32 vs int64 edge_index (int64 values < 2^31 -> hi words all zero).
__global__ void detect_kernel(const int* __restrict__ ei, int E) {
    if (threadIdx.x == 0) {
        int nz_hi = 0;
        int lim = (E > 64) ? 64 : E;
        for (int k = 0; k < lim; k++)
            if (ei[2 * k + 1] != 0) nz_hi++;
        g_is64 = (nz_hi == 0) ? 1 : 0;
    }
}

// Decode edge_index -> (src,dst) pairs + per-dst counts.
__global__ void decode_kernel(const int* __restrict__ ei, int E, int n) {
    const int is64 = g_is64;
    int stride = gridDim.x * blockDim.x;
    for (int i = blockIdx.x * blockDim.x + threadIdx.x; i < E; i += stride) {
        int s, d;
        if (is64) { s = ei[2 * i];  d = ei[2 * E + 2 * i]; }
        else      { s = ei[i];      d = ei[E + i]; }
        if ((unsigned)s >= (unsigned)n) { atomicOr(&g_diag, 4); s = 0; }
        if ((unsigned)d >= (unsigned)n) { atomicOr(&g_diag, 4); d = 0; }
        g_sd[i] = make_int2(s, d);
        atomicAdd(&g_cnt[d], 1);
    }
}

// Copy edge_attr [E,11] into 16B-aligned 12-float rows (coalesced).
__global__ void copy_ea_kernel(const float* __restrict__ ea, int E) {
    float* dst = reinterpret_cast<float*>(g_ea16);
    int total = E * D_EDGE;
    int stride = gridDim.x * blockDim.x;
    for (int i = blockIdx.x * blockDim.x + threadIdx.x; i < total; i += stride) {
        int e = i / D_EDGE, j = i - e * D_EDGE;
        dst[e * 12 + j] = ea[i];
    }
}

// ---- 3-kernel exclusive scan over g_cnt -> g_off ---------------------------
__global__ void scanA_kernel(int n) {
    __shared__ int s[SCAN_BLK];
    int t = threadIdx.x;
    int idx = blockIdx.x * SCAN_BLK + t;
    int v = (idx < n) ? g_cnt[idx] : 0;
    s[t] = v; __syncthreads();
    for (int off = 1; off < SCAN_BLK; off <<= 1) {
        int x = (t >= off) ? s[t - off] : 0;
        __syncthreads();
        s[t] += x;
        __syncthreads();
    }
    if (idx < n) g_off[idx] = s[t] - v;          // exclusive
    if (t == SCAN_BLK - 1) g_bsum[blockIdx.x] = s[t];
}

__global__ void scanB_kernel(int nblk) {
    if (threadIdx.x == 0) {
        int run = 0;
        for (int b = 0; b < nblk; b++) { int t = g_bsum[b]; g_bsum[b] = run; run += t; }
    }
}

__global__ void scanC_kernel(int n) {
    int idx = blockIdx.x * SCAN_BLK + threadIdx.x;
    if (idx < n) {
        int o = g_off[idx] + g_bsum[blockIdx.x];
        g_off[idx] = o;
        g_cursor[idx] = o;
    }
}

// Scatter edges into CSR buckets (integer atomics only).
__global__ void scatter_kernel(int E) {
    int stride = gridDim.x * blockDim.x;
    for (int i = blockIdx.x * blockDim.x + threadIdx.x; i < E; i += stride) {
        int2 sd = g_sd[i];
        int pos = atomicAdd(&g_cursor[sd.y], 1);
        g_csr[pos] = make_int2(sd.x, i);
    }
}

__global__ void diag_apply_kernel(float* __restrict__ out, int total) {
    const int diag = g_diag;
    if (diag == 0) return;
    float v = 0.f;
    if (diag & 4) v = 1e16f;
    if (diag & 8) v = 1e20f;
    int stride = gridDim.x * blockDim.x;
    for (int i = blockIdx.x * blockDim.x + threadIdx.x; i < total; i += stride)
        out[i] = v;
}

// ---------------------------------------------------------------------------
// GEMM (R4 baseline, measured 71.4us): g_x{l,r}[n,64] = x[n,128] @ W[128,64].
// ---------------------------------------------------------------------------
__global__ __launch_bounds__(256) void gemm_kernel(
    const float* __restrict__ x, const float* __restrict__ W,
    int n, int which)
{
    float* __restrict__ out = which ? g_xr : g_xl;   // device-side symbol

    __shared__ float sW[D_IN * D_OUT];  // 32 KB
    for (int i = threadIdx.x; i < D_IN * D_OUT / 4; i += 256) {
        reinterpret_cast<float4*>(sW)[i] = reinterpret_cast<const float4*>(W)[i];
    }
    __syncthreads();

    const int cg   = threadIdx.x & 7;
    const int rg   = threadIdx.x >> 3;
    const int row0 = blockIdx.x * 128 + rg * 4;

    float acc[4][8];
#pragma unroll
    for (int r = 0; r < 4; r++)
#pragma unroll
        for (int c = 0; c < 8; c++) acc[r][c] = 0.0f;

    for (int k = 0; k < D_IN; k += 4) {
        float xk[4][4];
#pragma unroll
        for (int r = 0; r < 4; r++) {
            int row = row0 + r;
            float4 v = make_float4(0.f, 0.f, 0.f, 0.f);
            if (row < n)
                v = *reinterpret_cast<const float4*>(x + (size_t)row * D_IN + k);
            xk[r][0] = v.x; xk[r][1] = v.y; xk[r][2] = v.z; xk[r][3] = v.w;
        }
#pragma unroll
        for (int kk = 0; kk < 4; kk++) {
            float4 w0 = *reinterpret_cast<const float4*>(&sW[(k + kk) * D_OUT + cg * 8]);
            float4 w1 = *reinterpret_cast<const float4*>(&sW[(k + kk) * D_OUT + cg * 8 + 4]);
#pragma unroll
            for (int r = 0; r < 4; r++) {
                float xv = xk[r][kk];
                acc[r][0] += xv * w0.x;  acc[r][1] += xv * w0.y;
                acc[r][2] += xv * w0.z;  acc[r][3] += xv * w0.w;
                acc[r][4] += xv * w1.x;  acc[r][5] += xv * w1.y;
                acc[r][6] += xv * w1.z;  acc[r][7] += xv * w1.w;
            }
        }
    }

#pragma unroll
    for (int r = 0; r < 4; r++) {
        int row = row0 + r;
        if (row < n) {
            float4* p = reinterpret_cast<float4*>(out + (size_t)row * D_OUT + cg * 8);
            p[0] = make_float4(acc[r][0], acc[r][1], acc[r][2], acc[r][3]);
            p[1] = make_float4(acc[r][4], acc[r][5], acc[r][6], acc[r][7]);
        }
    }
}

// ---------------------------------------------------------------------------
// Fused node kernel: warp per dst node; 2 half-warps process 2 edges per
// iteration; within a half, 16 lanes own 4 output cols each. No fp atomics.
//   per edge:  e   = attr @ We  (4 cols/lane)
//              p   = lrelu(xl[src]+xr[i]+e) . att  -> 4-shfl reduce in half
//              ex  = exp(p)   (max-free softmax; |logit| small)
//              acc += ex*xl[src]; den += ex; eacc += e
//   epilogue:  combine halves (shfl_xor 16); self-loop with eacc/deg;
//              out = (acc + ex_s*xl[i]) / (den + ex_s)
// ---------------------------------------------------------------------------
__global__ __launch_bounds__(128, 4) void node_kernel(
    const float* __restrict__ We, const float* __restrict__ att,
    float* __restrict__ out, int n)
{
    const int lane = threadIdx.x & 31;
    const int half = lane >> 4;
    const int sub  = lane & 15;
    const int cb   = sub * 4;
    const int node = (blockIdx.x * blockDim.x + threadIdx.x) >> 5;
    if (node >= n) return;

    float4 wev[D_EDGE];
#pragma unroll
    for (int j = 0; j < D_EDGE; j++)
        wev[j] = *reinterpret_cast<const float4*>(We + j * D_OUT + cb);
    const float4 at  = *reinterpret_cast<const float4*>(att + cb);

    const float4 vr  = *reinterpret_cast<const float4*>(g_xr + (size_t)node * D_OUT + cb);
    const float4 vli = *reinterpret_cast<const float4*>(g_xl + (size_t)node * D_OUT + cb);

    const int start = g_off[node];
    const int deg   = g_cnt[node];

    float a0 = 0.f, a1 = 0.f, a2 = 0.f, a3 = 0.f;   // acc (this half's edges)
    float den = 0.f;
    float ea0 = 0.f, ea1 = 0.f, ea2 = 0.f, ea3 = 0.f; // e-term sums

    for (int kb = 0; kb < deg; kb += 2) {
        const int  k     = kb + half;
        const bool valid = (k < deg);
        const int  kc    = valid ? k : kb;          // clamp (kb < deg always)

        const int2 ce = g_csr[start + kc];          // (src, eid): uniform in half
        const float4* ap = g_ea16 + (size_t)ce.y * 3;
        const float4 q0 = __ldg(ap);
        const float4 q1 = __ldg(ap + 1);
        const float4 q2 = __ldg(ap + 2);
        const float4 vl = *reinterpret_cast<const float4*>(
            g_xl + (size_t)ce.x * D_OUT + cb);

        float e0 = q0.x*wev[0].x + q0.y*wev[1].x + q0.z*wev[2].x + q0.w*wev[3].x
                 + q1.x*wev[4].x + q1.y*wev[5].x + q1.z*wev[6].x + q1.w*wev[7].x
                 + q2.x*wev[8].x + q2.y*wev[9].x + q2.z*wev[10].x;
        float e1 = q0.x*wev[0].y + q0.y*wev[1].y + q0.z*wev[2].y + q0.w*wev[3].y
                 + q1.x*wev[4].y + q1.y*wev[5].y + q1.z*wev[6].y + q1.w*wev[7].y
                 + q2.x*wev[8].y + q2.y*wev[9].y + q2.z*wev[10].y;
        float e2 = q0.x*wev[0].z + q0.y*wev[1].z + q0.z*wev[2].z + q0.w*wev[3].z
                 + q1.x*wev[4].z + q1.y*wev[5].z + q1.z*wev[6].z + q1.w*wev[7].z
                 + q2.x*wev[8].z + q2.y*wev[9].z + q2.z*wev[10].z;
        float e3 = q0.x*wev[0].w + q0.y*wev[1].w + q0.z*wev[2].w + q0.w*wev[3].w
                 + q1.x*wev[4].w + q1.y*wev[5].w + q1.z*wev[6].w + q1.w*wev[7].w
                 + q2.x*wev[8].w + q2.y*wev[9].w + q2.z*wev[10].w;

        float m0 = vl.x + vr.x + e0;
        float m1 = vl.y + vr.y + e1;
        float m2 = vl.z + vr.z + e2;
        float m3 = vl.w + vr.w + e3;
        m0 = (m0 >= 0.f) ? m0 : NEG_SLOPE * m0;
        m1 = (m1 >= 0.f) ? m1 : NEG_SLOPE * m1;
        m2 = (m2 >= 0.f) ? m2 : NEG_SLOPE * m2;
        m3 = (m3 >= 0.f) ? m3 : NEG_SLOPE * m3;
        float p = m0 * at.x + m1 * at.y + m2 * at.z + m3 * at.w;
#pragma unroll
        for (int o = 8; o > 0; o >>= 1)            // reduce within the half
            p += __shfl_xor_sync(0xffffffffu, p, o);

        const float ex = valid ? __expf(p) : 0.f;

        a0 += ex * vl.x;  a1 += ex * vl.y;
        a2 += ex * vl.z;  a3 += ex * vl.w;
        den += ex;
        if (valid) { ea0 += e0; ea1 += e1; ea2 += e2; ea3 += e3; }
    }

    // Combine the two halves (same cols, partial sums over even/odd edges).
    a0  += __shfl_xor_sync(0xffffffffu, a0, 16);
    a1  += __shfl_xor_sync(0xffffffffu, a1, 16);
    a2  += __shfl_xor_sync(0xffffffffu, a2, 16);
    a3  += __shfl_xor_sync(0xffffffffu, a3, 16);
    den += __shfl_xor_sync(0xffffffffu, den, 16);
    ea0 += __shfl_xor_sync(0xffffffffu, ea0, 16);
    ea1 += __shfl_xor_sync(0xffffffffu, ea1, 16);
    ea2 += __shfl_xor_sync(0xffffffffu, ea2, 16);
    ea3 += __shfl_xor_sync(0xffffffffu, ea3, 16);

    // Self-loop: loop_attr@We = eacc / max(deg,1)
    const float inv_deg = 1.0f / fmaxf((float)deg, 1.0f);
    float m0 = vli.x + vr.x + ea0 * inv_deg;
    float m1 = vli.y + vr.y + ea1 * inv_deg;
    float m2 = vli.z + vr.z + ea2 * inv_deg;
    float m3 = vli.w + vr.w + ea3 * inv_deg;
    m0 = (m0 >= 0.f) ? m0 : NEG_SLOPE * m0;
    m1 = (m1 >= 0.f) ? m1 : NEG_SLOPE * m1;
    m2 = (m2 >= 0.f) ? m2 : NEG_SLOPE * m2;
    m3 = (m3 >= 0.f) ? m3 : NEG_SLOPE * m3;
    float p = m0 * at.x + m1 * at.y + m2 * at.z + m3 * at.w;
#pragma unroll
    for (int o = 8; o > 0; o >>= 1)
        p += __shfl_xor_sync(0xffffffffu, p, o);
    const float exs = __expf(p);

    if (half == 0) {
        const float invd = 1.0f / (den + exs);
        float4 o;
        o.x = (a0 + exs * vli.x) * invd;
        o.y = (a1 + exs * vli.y) * invd;
        o.z = (a2 + exs * vli.z) * invd;
        o.w = (a3 + exs * vli.w) * invd;
        *reinterpret_cast<float4*>(out + (size_t)node * D_OUT + cb) = o;
    }
}

// ---------------------------------------------------------------------------
extern "C" void kernel_launch(void* const* d_in, const int* in_sizes, int n_in,
                              void* d_out, int out_size)
{
    const float *x = nullptr, *ea = nullptr, *Wl = nullptr, *Wr = nullptr;
    const float *We = nullptr, *att = nullptr;
    const int   *ei = nullptr;
    long long E = 0;
    int n = 0;

    for (int i = 0; i < n_in; i++) {               // pass 1: edge_attr
        long long s = in_sizes[i];
        if (s > 100000 && s % D_EDGE == 0) { ea = (const float*)d_in[i]; E = s / D_EDGE; }
    }
    for (int i = 0; i < n_in; i++) {               // pass 2: everything else
        long long s = in_sizes[i];
        const void* p = d_in[i];
        if (p == (const void*)ea) continue;
        if      (E > 0 && (s == 2 * E || s == 4 * E)) { ei = (const int*)p; }
        else if (s == D_IN * D_OUT)   { if (!Wl) Wl = (const float*)p; else Wr = (const float*)p; }
        else if (s == D_EDGE * D_OUT) { We  = (const float*)p; }
        else if (s == D_OUT)          { att = (const float*)p; }
        else if (s > 100000 && s % D_IN == 0) { x = (const float*)p; n = (int)(s / D_IN); }
    }

    float* out = (float*)d_out;
    const int total_out = out_size;

    if (!x || !ea || !ei || !Wl || !Wr || !We || !att || n <= 0 || E <= 0 ||
        n > NMAX || E > EMAX) {
        set_diag_kernel<<<1, 32>>>(8);
        diag_apply_kernel<<<512, 256>>>(out, total_out);
        return;
    }
    const int Ei = (int)E;
    const int nblk = (n + SCAN_BLK - 1) / SCAN_BLK;

    init_kernel<<<256, 256>>>(n);
    detect_kernel<<<1, 32>>>(ei, Ei);
    decode_kernel<<<512, 256>>>(ei, Ei, n);
    copy_ea_kernel<<<2048, 256>>>(ea, Ei);

    scanA_kernel<<<nblk, SCAN_BLK>>>(n);
    scanB_kernel<<<1, 32>>>(nblk);
    scanC_kernel<<<nblk, SCAN_BLK>>>(n);
    scatter_kernel<<<512, 256>>>(Ei);

    gemm_kernel<<<(n + 127) / 128, 256>>>(x, Wl, n, 0);  // -> g_xl
    gemm_kernel<<<(n + 127) / 128, 256>>>(x, Wr, n, 1);  // -> g_xr

    node_kernel<<<(n * 32 + 127) / 128, 128>>>(We, att, out, n);

    diag_apply_kernel<<<512, 256>>>(out, total_out);
}

// round 8
// speedup vs baseline: 1.3302x; 1.3302x over previous
#include <cuda_runtime.h>
#include <cstdint>

#define D_IN   128
#define D_OUT  64
#define D_EDGE 11
#define NMAX   100000
#define EMAX   1000000
#define NEG_SLOPE 0.2f

// Scratch: ONLY referenced from device code (host-side use of a __device__
// symbol passes the host shadow address; ATS silently dereferences it).
__device__ float g_xl[(size_t)NMAX * D_OUT];     // x @ W_l
__device__ float g_xr[(size_t)NMAX * D_OUT];     // x @ W_r
__device__ float g_lsum[(size_t)NMAX * D_EDGE];  // sum of incoming edge_attr per dst
__device__ float g_deg[NMAX];                    // in-degree (float)
__device__ float g_denom[NMAX];                  // sum of exp(logit) per dst
__device__ int2  g_sd[EMAX];                     // decoded (src, dst)
__device__ int   g_is64;
__device__ int   g_diag;

// ---------------------------------------------------------------------------
// Zero output + accumulators; detect int32 vs int64 edge_index (int64 values
// < 2^31 -> hi words of first 64 entries all zero; P[false pos] ~ 1e-320).
// ---------------------------------------------------------------------------
__global__ void init_kernel(float* __restrict__ out, int out_total,
                            const int* __restrict__ ei, int E, int n) {
    int stride = gridDim.x * blockDim.x;
    int tid0 = blockIdx.x * blockDim.x + threadIdx.x;
    if (tid0 == 0) {
        g_diag = 0;
        int nz_hi = 0;
        int lim = (E > 64) ? 64 : E;
        for (int k = 0; k < lim; k++)
            if (ei[2 * k + 1] != 0) nz_hi++;
        g_is64 = (nz_hi == 0) ? 1 : 0;
    }
    for (int i = tid0; i < out_total; i += stride) out[i] = 0.0f;
    int total = n * D_EDGE;
    for (int i = tid0; i < total; i += stride) {
        g_lsum[i] = 0.0f;
        if (i < n) { g_deg[i] = 0.0f; g_denom[i] = 0.0f; }
    }
}

__global__ void set_diag_kernel(int bits) {
    if (threadIdx.x == 0) atomicOr(&g_diag, bits);
}

// Decode edge_index -> (src,dst) int2, bounds-checked.
__global__ void decode_kernel(const int* __restrict__ ei, int E, int n) {
    const int is64 = g_is64;
    int stride = gridDim.x * blockDim.x;
    for (int i = blockIdx.x * blockDim.x + threadIdx.x; i < E; i += stride) {
        int s, d;
        if (is64) { s = ei[2 * i];  d = ei[2 * E + 2 * i]; }
        else      { s = ei[i];      d = ei[E + i]; }
        if ((unsigned)s >= (unsigned)n) { atomicOr(&g_diag, 4); s = 0; }
        if ((unsigned)d >= (unsigned)n) { atomicOr(&g_diag, 4); d = 0; }
        g_sd[i] = make_int2(s, d);
    }
}

__global__ void diag_apply_kernel(float* __restrict__ out, int total) {
    const int diag = g_diag;
    if (diag == 0) return;
    float v = 0.f;
    if (diag & 4) v = 1e16f;
    if (diag & 8) v = 1e20f;
    int stride = gridDim.x * blockDim.x;
    for (int i = blockIdx.x * blockDim.x + threadIdx.x; i < total; i += stride)
        out[i] = v;
}

// ---------------------------------------------------------------------------
// GEMM (measured 71.4us): g_x{l,r}[n,64] = x[n,128] @ W[128,64].
// ---------------------------------------------------------------------------
__global__ __launch_bounds__(256) void gemm_kernel(
    const float* __restrict__ x, const float* __restrict__ W,
    int n, int which)
{
    float* __restrict__ out = which ? g_xr : g_xl;   // device-side symbol

    __shared__ float sW[D_IN * D_OUT];  // 32 KB
    for (int i = threadIdx.x; i < D_IN * D_OUT / 4; i += 256) {
        reinterpret_cast<float4*>(sW)[i] = reinterpret_cast<const float4*>(W)[i];
    }
    __syncthreads();

    const int cg   = threadIdx.x & 7;
    const int rg   = threadIdx.x >> 3;
    const int row0 = blockIdx.x * 128 + rg * 4;

    float acc[4][8];
#pragma unroll
    for (int r = 0; r < 4; r++)
#pragma unroll
        for (int c = 0; c < 8; c++) acc[r][c] = 0.0f;

    for (int k = 0; k < D_IN; k += 4) {
        float xk[4][4];
#pragma unroll
        for (int r = 0; r < 4; r++) {
            int row = row0 + r;
            float4 v = make_float4(0.f, 0.f, 0.f, 0.f);
            if (row < n)
                v = *reinterpret_cast<const float4*>(x + (size_t)row * D_IN + k);
            xk[r][0] = v.x; xk[r][1] = v.y; xk[r][2] = v.z; xk[r][3] = v.w;
        }
#pragma unroll
        for (int kk = 0; kk < 4; kk++) {
            float4 w0 = *reinterpret_cast<const float4*>(&sW[(k + kk) * D_OUT + cg * 8]);
            float4 w1 = *reinterpret_cast<const float4*>(&sW[(k + kk) * D_OUT + cg * 8 + 4]);
#pragma unroll
            for (int r = 0; r < 4; r++) {
                float xv = xk[r][kk];
                acc[r][0] += xv * w0.x;  acc[r][1] += xv * w0.y;
                acc[r][2] += xv * w0.z;  acc[r][3] += xv * w0.w;
                acc[r][4] += xv * w1.x;  acc[r][5] += xv * w1.y;
                acc[r][6] += xv * w1.z;  acc[r][7] += xv * w1.w;
            }
        }
    }

#pragma unroll
    for (int r = 0; r < 4; r++) {
        int row = row0 + r;
        if (row < n) {
            float4* p = reinterpret_cast<float4*>(out + (size_t)row * D_OUT + cg * 8);
            p[0] = make_float4(acc[r][0], acc[r][1], acc[r][2], acc[r][3]);
            p[1] = make_float4(acc[r][4], acc[r][5], acc[r][6], acc[r][7]);
        }
    }
}

// ---------------------------------------------------------------------------
// Edge pass: 2 edges per warp; 16 lanes per edge, 4 output cols per lane.
// Attr row (11 floats) is loaded ONE ELEMENT PER LANE (single warp LDG) and
// broadcast via shuffles -> LSU issue per edge collapses from ~20 to ~4.
//  logit = leakyrelu(xl[src] + xr[dst] + attr@We) . att   (max-free softmax)
//  out[dst] += ex*xl[src] (red.v4);  denom+=ex; lsum+=attr; deg+=1
// ---------------------------------------------------------------------------
__device__ __forceinline__ void red_add_v4(float* p, float a, float b, float c, float d) {
    asm volatile("red.global.add.v4.f32 [%0], {%1,%2,%3,%4};"
                 :: "l"(p), "f"(a), "f"(b), "f"(c), "f"(d) : "memory");
}

__global__ __launch_bounds__(256) void edge_kernel(
    const float* __restrict__ ea,
    const float* __restrict__ We, const float* __restrict__ att,
    float* __restrict__ out, int E)
{
    const int lane   = threadIdx.x & 31;
    const int half   = lane >> 4;          // which edge of the pair
    const int sub    = lane & 15;          // lane within edge group
    const int cb     = sub * 4;            // 4 output cols per lane
    const int hbase  = half << 4;          // shfl source base for this half
    const int warp   = (blockIdx.x * blockDim.x + threadIdx.x) >> 5;
    const int nwarps = (gridDim.x * blockDim.x) >> 5;

    // Per-lane 4-column slice of W_e and att, in registers.
    float4 wev[D_EDGE];
#pragma unroll
    for (int j = 0; j < D_EDGE; j++)
        wev[j] = *reinterpret_cast<const float4*>(We + j * D_OUT + cb);
    const float4 at = *reinterpret_cast<const float4*>(att + cb);

    for (int e0 = warp * 2; e0 < E; e0 += nwarps * 2) {
        const int  e     = e0 + half;
        const bool valid = (e < E);
        const int  ec    = valid ? e : e0;

        const int2 sd = g_sd[ec];
        // One warp LDG: lanes 0..10 of each half fetch this edge's attr row.
        const float av = (sub < D_EDGE) ? __ldg(ea + (size_t)ec * D_EDGE + sub) : 0.f;

        const float4 vl = *reinterpret_cast<const float4*>(
            g_xl + (size_t)sd.x * D_OUT + cb);
        const float4 vr = *reinterpret_cast<const float4*>(
            g_xr + (size_t)sd.y * D_OUT + cb);

        // e-term: attr @ We via shuffle-broadcast of the 11 attr values.
        float e0c = 0.f, e1c = 0.f, e2c = 0.f, e3c = 0.f;
#pragma unroll
        for (int j = 0; j < D_EDGE; j++) {
            const float aj = __shfl_sync(0xffffffffu, av, hbase + j);
            e0c += aj * wev[j].x;
            e1c += aj * wev[j].y;
            e2c += aj * wev[j].z;
            e3c += aj * wev[j].w;
        }

        float m0 = vl.x + vr.x + e0c;
        float m1 = vl.y + vr.y + e1c;
        float m2 = vl.z + vr.z + e2c;
        float m3 = vl.w + vr.w + e3c;
        m0 = (m0 >= 0.f) ? m0 : NEG_SLOPE * m0;
        m1 = (m1 >= 0.f) ? m1 : NEG_SLOPE * m1;
        m2 = (m2 >= 0.f) ? m2 : NEG_SLOPE * m2;
        m3 = (m3 >= 0.f) ? m3 : NEG_SLOPE * m3;
        float p = m0 * at.x + m1 * at.y + m2 * at.z + m3 * at.w;
#pragma unroll
        for (int o = 8; o > 0; o >>= 1)          // reduce within the half
            p += __shfl_xor_sync(0xffffffffu, p, o);
        const float ex = __expf(p);

        if (valid) {
            red_add_v4(out + (size_t)sd.y * D_OUT + cb,
                       ex * vl.x, ex * vl.y, ex * vl.z, ex * vl.w);
            if (sub == 0)           atomicAdd(&g_denom[sd.y], ex);
            if (sub < D_EDGE)       atomicAdd(&g_lsum[(size_t)sd.y * D_EDGE + sub], av);
            else if (sub == D_EDGE) atomicAdd(&g_deg[sd.y], 1.0f);
        }
    }
}

// ---------------------------------------------------------------------------
// Finalize: 2 nodes per warp (16 lanes x 4 cols). Self-loop term + normalize.
// ---------------------------------------------------------------------------
__global__ __launch_bounds__(256) void final_kernel(
    const float* __restrict__ We, const float* __restrict__ att,
    float* __restrict__ out, int n)
{
    const int lane   = threadIdx.x & 31;
    const int half   = lane >> 4;
    const int sub    = lane & 15;
    const int cb     = sub * 4;
    const int warp   = (blockIdx.x * blockDim.x + threadIdx.x) >> 5;
    const int nwarps = (gridDim.x * blockDim.x) >> 5;

    float4 wev[D_EDGE];
#pragma unroll
    for (int j = 0; j < D_EDGE; j++)
        wev[j] = *reinterpret_cast<const float4*>(We + j * D_OUT + cb);
    const float4 at = *reinterpret_cast<const float4*>(att + cb);

    for (int i0 = warp * 2; i0 < n; i0 += nwarps * 2) {
        const int  i     = i0 + half;
        const bool valid = (i < n);
        const int  ic    = valid ? i : i0;

        const float inv_deg = 1.0f / fmaxf(g_deg[ic], 1.0f);

        float e0c = 0.f, e1c = 0.f, e2c = 0.f, e3c = 0.f;
#pragma unroll
        for (int j = 0; j < D_EDGE; j++) {
            const float la = g_lsum[(size_t)ic * D_EDGE + j] * inv_deg;
            e0c += la * wev[j].x;
            e1c += la * wev[j].y;
            e2c += la * wev[j].z;
            e3c += la * wev[j].w;
        }

        const float4 vl = *reinterpret_cast<const float4*>(g_xl + (size_t)ic * D_OUT + cb);
        const float4 vr = *reinterpret_cast<const float4*>(g_xr + (size_t)ic * D_OUT + cb);

        float m0 = vl.x + vr.x + e0c;
        float m1 = vl.y + vr.y + e1c;
        float m2 = vl.z + vr.z + e2c;
        float m3 = vl.w + vr.w + e3c;
        m0 = (m0 >= 0.f) ? m0 : NEG_SLOPE * m0;
        m1 = (m1 >= 0.f) ? m1 : NEG_SLOPE * m1;
        m2 = (m2 >= 0.f) ? m2 : NEG_SLOPE * m2;
        m3 = (m3 >= 0.f) ? m3 : NEG_SLOPE * m3;
        float p = m0 * at.x + m1 * at.y + m2 * at.z + m3 * at.w;
#pragma unroll
        for (int o = 8; o > 0; o >>= 1)
            p += __shfl_xor_sync(0xffffffffu, p, o);
        const float ex = __expf(p);

        if (valid) {
            const float invd = 1.0f / (g_denom[ic] + ex);
            float* op = out + (size_t)ic * D_OUT + cb;
            float4 o = *reinterpret_cast<float4*>(op);
            o.x = (o.x + ex * vl.x) * invd;
            o.y = (o.y + ex * vl.y) * invd;
            o.z = (o.z + ex * vl.z) * invd;
            o.w = (o.w + ex * vl.w) * invd;
            *reinterpret_cast<float4*>(op) = o;
        }
    }
}

// ---------------------------------------------------------------------------
extern "C" void kernel_launch(void* const* d_in, const int* in_sizes, int n_in,
                              void* d_out, int out_size)
{
    const float *x = nullptr, *ea = nullptr, *Wl = nullptr, *Wr = nullptr;
    const float *We = nullptr, *att = nullptr;
    const int   *ei = nullptr;
    long long E = 0;
    int n = 0;

    for (int i = 0; i < n_in; i++) {               // pass 1: edge_attr
        long long s = in_sizes[i];
        if (s > 100000 && s % D_EDGE == 0) { ea = (const float*)d_in[i]; E = s / D_EDGE; }
    }
    for (int i = 0; i < n_in; i++) {               // pass 2: everything else
        long long s = in_sizes[i];
        const void* p = d_in[i];
        if (p == (const void*)ea) continue;
        if      (E > 0 && (s == 2 * E || s == 4 * E)) { ei = (const int*)p; }
        else if (s == D_IN * D_OUT)   { if (!Wl) Wl = (const float*)p; else Wr = (const float*)p; }
        else if (s == D_EDGE * D_OUT) { We  = (const float*)p; }
        else if (s == D_OUT)          { att = (const float*)p; }
        else if (s > 100000 && s % D_IN == 0) { x = (const float*)p; n = (int)(s / D_IN); }
    }

    float* out = (float*)d_out;
    const int total_out = out_size;

    if (!x || !ea || !ei || !Wl || !Wr || !We || !att || n <= 0 || E <= 0 ||
        n > NMAX || E > EMAX) {
        set_diag_kernel<<<1, 32>>>(8);
        diag_apply_kernel<<<512, 256>>>(out, total_out);
        return;
    }
    const int Ei = (int)E;

    init_kernel<<<1024, 256>>>(out, total_out, ei, Ei, n);
    decode_kernel<<<512, 256>>>(ei, Ei, n);

    gemm_kernel<<<(n + 127) / 128, 256>>>(x, Wl, n, 0);  // -> g_xl
    gemm_kernel<<<(n + 127) / 128, 256>>>(x, Wr, n, 1);  // -> g_xr

    edge_kernel<<<4096, 256>>>(ea, We, att, out, Ei);
    final_kernel<<<2048, 256>>>(We, att, out, n);

    diag_apply_kernel<<<512, 256>>>(out, total_out);
}

// round 9
// speedup vs baseline: 1.4011x; 1.0533x over previous
#include <cuda_runtime.h>
#include <cstdint>

#define D_IN   128
#define D_OUT  64
#define D_EDGE 11
#define NMAX   100000
#define EMAX   1000000
#define NEG_SLOPE 0.2f

// Scratch: ONLY referenced from device code (host-side use of a __device__
// symbol passes the host shadow address; ATS silently dereferences it).
__device__ float g_xl[(size_t)NMAX * D_OUT];     // x @ W_l
__device__ float g_xr[(size_t)NMAX * D_OUT];     // x @ W_r
__device__ float g_lsum[(size_t)NMAX * 12];      // [0..10]=sum attr, [11]=deg
__device__ float g_denom[NMAX];                  // sum of exp(logit) per dst
__device__ int2  g_sd[EMAX];                     // decoded (src, dst)
__device__ int   g_is64;
__device__ int   g_diag;

// ---------------------------------------------------------------------------
// Zero output + accumulators; detect int32 vs int64 edge_index (int64 values
// < 2^31 -> hi words of first 64 entries all zero).
// ---------------------------------------------------------------------------
__global__ void init_kernel(float* __restrict__ out, int out_total,
                            const int* __restrict__ ei, int E, int n) {
    int stride = gridDim.x * blockDim.x;
    int tid0 = blockIdx.x * blockDim.x + threadIdx.x;
    if (tid0 == 0) {
        g_diag = 0;
        int nz_hi = 0;
        int lim = (E > 64) ? 64 : E;
        for (int k = 0; k < lim; k++)
            if (ei[2 * k + 1] != 0) nz_hi++;
        g_is64 = (nz_hi == 0) ? 1 : 0;
    }
    for (int i = tid0; i < out_total; i += stride) out[i] = 0.0f;
    int total = n * 12;
    for (int i = tid0; i < total; i += stride) {
        g_lsum[i] = 0.0f;
        if (i < n) g_denom[i] = 0.0f;
    }
}

__global__ void set_diag_kernel(int bits) {
    if (threadIdx.x == 0) atomicOr(&g_diag, bits);
}

// Decode edge_index -> (src,dst) int2, bounds-checked.
__global__ void decode_kernel(const int* __restrict__ ei, int E, int n) {
    const int is64 = g_is64;
    int stride = gridDim.x * blockDim.x;
    for (int i = blockIdx.x * blockDim.x + threadIdx.x; i < E; i += stride) {
        int s, d;
        if (is64) { s = ei[2 * i];  d = ei[2 * E + 2 * i]; }
        else      { s = ei[i];      d = ei[E + i]; }
        if ((unsigned)s >= (unsigned)n) { atomicOr(&g_diag, 4); s = 0; }
        if ((unsigned)d >= (unsigned)n) { atomicOr(&g_diag, 4); d = 0; }
        g_sd[i] = make_int2(s, d);
    }
}

__global__ void diag_apply_kernel(float* __restrict__ out, int total) {
    const int diag = g_diag;
    if (diag == 0) return;
    float v = 0.f;
    if (diag & 4) v = 1e16f;
    if (diag & 8) v = 1e20f;
    int stride = gridDim.x * blockDim.x;
    for (int i = blockIdx.x * blockDim.x + threadIdx.x; i < total; i += stride)
        out[i] = v;
}

// ---------------------------------------------------------------------------
// GEMM: g_x{l,r}[n,64] = x[n,128] @ W[128,64].
// Bank-conflict-free W reads: thread cg owns cols {cg*4..+3} and {32+cg*4..+3},
// so each LDS.128 across cg=0..7 touches words cg*4 -> all 32 banks exactly
// once (the old cg*8 mapping hit banks {0-3,8-11,16-19,24-27} twice).
// ---------------------------------------------------------------------------
__global__ __launch_bounds__(256) void gemm_kernel(
    const float* __restrict__ x, const float* __restrict__ W,
    int n, int which)
{
    float* __restrict__ out = which ? g_xr : g_xl;   // device-side symbol

    __shared__ float sW[D_IN * D_OUT];  // 32 KB
    for (int i = threadIdx.x; i < D_IN * D_OUT / 4; i += 256) {
        reinterpret_cast<float4*>(sW)[i] = reinterpret_cast<const float4*>(W)[i];
    }
    __syncthreads();

    const int cg   = threadIdx.x & 7;
    const int rg   = threadIdx.x >> 3;
    const int row0 = blockIdx.x * 128 + rg * 4;
    const float4* sW4 = reinterpret_cast<const float4*>(sW);

    float acc0[4][4], acc1[4][4];     // cols cg*4..+3 and 32+cg*4..+3
#pragma unroll
    for (int r = 0; r < 4; r++)
#pragma unroll
        for (int c = 0; c < 4; c++) { acc0[r][c] = 0.f; acc1[r][c] = 0.f; }

    for (int k = 0; k < D_IN; k += 4) {
        float xk[4][4];
#pragma unroll
        for (int r = 0; r < 4; r++) {
            int row = row0 + r;
            float4 v = make_float4(0.f, 0.f, 0.f, 0.f);
            if (row < n)
                v = *reinterpret_cast<const float4*>(x + (size_t)row * D_IN + k);
            xk[r][0] = v.x; xk[r][1] = v.y; xk[r][2] = v.z; xk[r][3] = v.w;
        }
#pragma unroll
        for (int kk = 0; kk < 4; kk++) {
            const float4 w0 = sW4[(k + kk) * 16 + cg];       // words cg*4: conflict-free
            const float4 w1 = sW4[(k + kk) * 16 + 8 + cg];   // words 32+cg*4: conflict-free
#pragma unroll
            for (int r = 0; r < 4; r++) {
                const float xv = xk[r][kk];
                acc0[r][0] += xv * w0.x;  acc0[r][1] += xv * w0.y;
                acc0[r][2] += xv * w0.z;  acc0[r][3] += xv * w0.w;
                acc1[r][0] += xv * w1.x;  acc1[r][1] += xv * w1.y;
                acc1[r][2] += xv * w1.z;  acc1[r][3] += xv * w1.w;
            }
        }
    }

#pragma unroll
    for (int r = 0; r < 4; r++) {
        int row = row0 + r;
        if (row < n) {
            *reinterpret_cast<float4*>(out + (size_t)row * D_OUT + cg * 4) =
                make_float4(acc0[r][0], acc0[r][1], acc0[r][2], acc0[r][3]);
            *reinterpret_cast<float4*>(out + (size_t)row * D_OUT + 32 + cg * 4) =
                make_float4(acc1[r][0], acc1[r][1], acc1[r][2], acc1[r][3]);
        }
    }
}

// ---------------------------------------------------------------------------
// Edge pass: 2 edges per warp; 16 lanes per edge, 4 output cols per lane.
// Attr row loaded one element per lane (single warp LDG), broadcast by shfl.
// Side accumulators packed: lsum[0..10] + count in [11] -> ONE v4 RED by 3
// lanes (was 12 scalar lane-ops); denom by 1 lane. 20 RED lane-ops/edge.
// ---------------------------------------------------------------------------
__device__ __forceinline__ void red_add_v4(float* p, float a, float b, float c, float d) {
    asm volatile("red.global.add.v4.f32 [%0], {%1,%2,%3,%4};"
                 :: "l"(p), "f"(a), "f"(b), "f"(c), "f"(d) : "memory");
}

__global__ __launch_bounds__(256) void edge_kernel(
    const float* __restrict__ ea,
    const float* __restrict__ We, const float* __restrict__ att,
    float* __restrict__ out, int E)
{
    const int lane   = threadIdx.x & 31;
    const int half   = lane >> 4;          // which edge of the pair
    const int sub    = lane & 15;          // lane within edge group
    const int cb     = sub * 4;            // 4 output cols per lane
    const int hbase  = half << 4;          // shfl source base for this half
    const int warp   = (blockIdx.x * blockDim.x + threadIdx.x) >> 5;
    const int nwarps = (gridDim.x * blockDim.x) >> 5;

    // Per-lane 4-column slice of W_e and att, in registers.
    float4 wev[D_EDGE];
#pragma unroll
    for (int j = 0; j < D_EDGE; j++)
        wev[j] = *reinterpret_cast<const float4*>(We + j * D_OUT + cb);
    const float4 at = *reinterpret_cast<const float4*>(att + cb);

    for (int e0 = warp * 2; e0 < E; e0 += nwarps * 2) {
        const int  e     = e0 + half;
        const bool valid = (e < E);
        const int  ec    = valid ? e : e0;

        const int2 sd = g_sd[ec];
        // One warp LDG: lanes 0..10 of each half fetch this edge's attr row.
        const float av = (sub < D_EDGE) ? __ldg(ea + (size_t)ec * D_EDGE + sub) : 0.f;

        const float4 vl = *reinterpret_cast<const float4*>(
            g_xl + (size_t)sd.x * D_OUT + cb);
        const float4 vr = *reinterpret_cast<const float4*>(
            g_xr + (size_t)sd.y * D_OUT + cb);

        // Broadcast the 11 attr values to all lanes (feeds e-term AND lsum).
        float aj[D_EDGE];
#pragma unroll
        for (int j = 0; j < D_EDGE; j++)
            aj[j] = __shfl_sync(0xffffffffu, av, hbase + j);

        float e0c = 0.f, e1c = 0.f, e2c = 0.f, e3c = 0.f;
#pragma unroll
        for (int j = 0; j < D_EDGE; j++) {
            e0c += aj[j] * wev[j].x;
            e1c += aj[j] * wev[j].y;
            e2c += aj[j] * wev[j].z;
            e3c += aj[j] * wev[j].w;
        }

        float m0 = vl.x + vr.x + e0c;
        float m1 = vl.y + vr.y + e1c;
        float m2 = vl.z + vr.z + e2c;
        float m3 = vl.w + vr.w + e3c;
        m0 = (m0 >= 0.f) ? m0 : NEG_SLOPE * m0;
        m1 = (m1 >= 0.f) ? m1 : NEG_SLOPE * m1;
        m2 = (m2 >= 0.f) ? m2 : NEG_SLOPE * m2;
        m3 = (m3 >= 0.f) ? m3 : NEG_SLOPE * m3;
        float p = m0 * at.x + m1 * at.y + m2 * at.z + m3 * at.w;
#pragma unroll
        for (int o = 8; o > 0; o >>= 1)          // reduce within the half
            p += __shfl_xor_sync(0xffffffffu, p, o);
        const float ex = __expf(p);

        if (valid) {
            red_add_v4(out + (size_t)sd.y * D_OUT + cb,
                       ex * vl.x, ex * vl.y, ex * vl.z, ex * vl.w);
            if (sub < 3) {
                // lanes 0,1,2 cover lsum[0..10] + count at [11] in one v4 RED
                const float b0 = (sub == 0) ? aj[0] : (sub == 1) ? aj[4] : aj[8];
                const float b1 = (sub == 0) ? aj[1] : (sub == 1) ? aj[5] : aj[9];
                const float b2 = (sub == 0) ? aj[2] : (sub == 1) ? aj[6] : aj[10];
                const float b3 = (sub == 0) ? aj[3] : (sub == 1) ? aj[7] : 1.0f;
                red_add_v4(&g_lsum[(size_t)sd.y * 12 + sub * 4], b0, b1, b2, b3);
            } else if (sub == 3) {
                atomicAdd(&g_denom[sd.y], ex);
            }
        }
    }
}

// ---------------------------------------------------------------------------
// Finalize: 2 nodes per warp (16 lanes x 4 cols). Self-loop term + normalize.
// ---------------------------------------------------------------------------
__global__ __launch_bounds__(256) void final_kernel(
    const float* __restrict__ We, const float* __restrict__ att,
    float* __restrict__ out, int n)
{
    const int lane   = threadIdx.x & 31;
    const int half   = lane >> 4;
    const int sub    = lane & 15;
    const int cb     = sub * 4;
    const int warp   = (blockIdx.x * blockDim.x + threadIdx.x) >> 5;
    const int nwarps = (gridDim.x * blockDim.x) >> 5;

    float4 wev[D_EDGE];
#pragma unroll
    for (int j = 0; j < D_EDGE; j++)
        wev[j] = *reinterpret_cast<const float4*>(We + j * D_OUT + cb);
    const float4 at = *reinterpret_cast<const float4*>(att + cb);

    for (int i0 = warp * 2; i0 < n; i0 += nwarps * 2) {
        const int  i     = i0 + half;
        const bool valid = (i < n);
        const int  ic    = valid ? i : i0;

        // lsum row: 3 uniform LDG.128 (broadcast); q2.w = deg count.
        const float4* lp = reinterpret_cast<const float4*>(g_lsum + (size_t)ic * 12);
        const float4 q0 = lp[0];
        const float4 q1 = lp[1];
        const float4 q2 = lp[2];
        const float inv_deg = 1.0f / fmaxf(q2.w, 1.0f);

        float e0c = q0.x*wev[0].x + q0.y*wev[1].x + q0.z*wev[2].x + q0.w*wev[3].x
                  + q1.x*wev[4].x + q1.y*wev[5].x + q1.z*wev[6].x + q1.w*wev[7].x
                  + q2.x*wev[8].x + q2.y*wev[9].x + q2.z*wev[10].x;
        float e1c = q0.x*wev[0].y + q0.y*wev[1].y + q0.z*wev[2].y + q0.w*wev[3].y
                  + q1.x*wev[4].y + q1.y*wev[5].y + q1.z*wev[6].y + q1.w*wev[7].y
                  + q2.x*wev[8].y + q2.y*wev[9].y + q2.z*wev[10].y;
        float e2c = q0.x*wev[0].z + q0.y*wev[1].z + q0.z*wev[2].z + q0.w*wev[3].z
                  + q1.x*wev[4].z + q1.y*wev[5].z + q1.z*wev[6].z + q1.w*wev[7].z
                  + q2.x*wev[8].z + q2.y*wev[9].z + q2.z*wev[10].z;
        float e3c = q0.x*wev[0].w + q0.y*wev[1].w + q0.z*wev[2].w + q0.w*wev[3].w
                  + q1.x*wev[4].w + q1.y*wev[5].w + q1.z*wev[6].w + q1.w*wev[7].w
                  + q2.x*wev[8].w + q2.y*wev[9].w + q2.z*wev[10].w;
        e0c *= inv_deg; e1c *= inv_deg; e2c *= inv_deg; e3c *= inv_deg;

        const float4 vl = *reinterpret_cast<const float4*>(g_xl + (size_t)ic * D_OUT + cb);
        const float4 vr = *reinterpret_cast<const float4*>(g_xr + (size_t)ic * D_OUT + cb);

        float m0 = vl.x + vr.x + e0c;
        float m1 = vl.y + vr.y + e1c;
        float m2 = vl.z + vr.z + e2c;
        float m3 = vl.w + vr.w + e3c;
        m0 = (m0 >= 0.f) ? m0 : NEG_SLOPE * m0;
        m1 = (m1 >= 0.f) ? m1 : NEG_SLOPE * m1;
        m2 = (m2 >= 0.f) ? m2 : NEG_SLOPE * m2;
        m3 = (m3 >= 0.f) ? m3 : NEG_SLOPE * m3;
        float p = m0 * at.x + m1 * at.y + m2 * at.z + m3 * at.w;
#pragma unroll
        for (int o = 8; o > 0; o >>= 1)
            p += __shfl_xor_sync(0xffffffffu, p, o);
        const float ex = __expf(p);

        if (valid) {
            const float invd = 1.0f / (g_denom[ic] + ex);
            float* op = out + (size_t)ic * D_OUT + cb;
            float4 o = *reinterpret_cast<float4*>(op);
            o.x = (o.x + ex * vl.x) * invd;
            o.y = (o.y + ex * vl.y) * invd;
            o.z = (o.z + ex * vl.z) * invd;
            o.w = (o.w + ex * vl.w) * invd;
            *reinterpret_cast<float4*>(op) = o;
        }
    }
}

// ---------------------------------------------------------------------------
extern "C" void kernel_launch(void* const* d_in, const int* in_sizes, int n_in,
                              void* d_out, int out_size)
{
    const float *x = nullptr, *ea = nullptr, *Wl = nullptr, *Wr = nullptr;
    const float *We = nullptr, *att = nullptr;
    const int   *ei = nullptr;
    long long E = 0;
    int n = 0;

    for (int i = 0; i < n_in; i++) {               // pass 1: edge_attr
        long long s = in_sizes[i];
        if (s > 100000 && s % D_EDGE == 0) { ea = (const float*)d_in[i]; E = s / D_EDGE; }
    }
    for (int i = 0; i < n_in; i++) {               // pass 2: everything else
        long long s = in_sizes[i];
        const void* p = d_in[i];
        if (p == (const void*)ea) continue;
        if      (E > 0 && (s == 2 * E || s == 4 * E)) { ei = (const int*)p; }
        else if (s == D_IN * D_OUT)   { if (!Wl) Wl = (const float*)p; else Wr = (const float*)p; }
        else if (s == D_EDGE * D_OUT) { We  = (const float*)p; }
        else if (s == D_OUT)          { att = (const float*)p; }
        else if (s > 100000 && s % D_IN == 0) { x = (const float*)p; n = (int)(s / D_IN); }
    }

    float* out = (float*)d_out;
    const int total_out = out_size;

    if (!x || !ea || !ei || !Wl || !Wr || !We || !att || n <= 0 || E <= 0 ||
        n > NMAX || E > EMAX) {
        set_diag_kernel<<<1, 32>>>(8);
        diag_apply_kernel<<<512, 256>>>(out, total_out);
        return;
    }
    const int Ei = (int)E;

    init_kernel<<<1024, 256>>>(out, total_out, ei, Ei, n);
    decode_kernel<<<512, 256>>>(ei, Ei, n);

    gemm_kernel<<<(n + 127) / 128, 256>>>(x, Wl, n, 0);  // -> g_xl
    gemm_kernel<<<(n + 127) / 128, 256>>>(x, Wr, n, 1);  // -> g_xr

    edge_kernel<<<4096, 256>>>(ea, We, att, out, Ei);
    final_kernel<<<2048, 256>>>(We, att, out, n);

    diag_apply_kernel<<<512, 256>>>(out, total_out);
}